// round 1
// baseline (speedup 1.0000x reference)
#include <cuda_runtime.h>

#define NN 100000
#define EE 1600000
#define EN (EE + NN)

// ---------------- scratch (device globals; no allocation allowed) ----------
__device__ float g_h1[NN * 128];   // conv1 linear output  (51.2 MB)
__device__ float g_out1[NN * 128]; // conv1 aggregated + relu (51.2 MB)
__device__ float g_w1[EN * 4];     // per-edge exp weights, 4 heads (27.2 MB)
__device__ float g_as1[NN * 4];
__device__ float g_ad1[NN * 4];
__device__ float g_den1[NN * 4];
__device__ float g_h2[NN * 32];    // conv2 linear output (12.8 MB)
__device__ float g_w2[EN];
__device__ float g_as2[NN];
__device__ float g_ad2[NN];
__device__ float g_den2[NN];

__device__ __forceinline__ float lrelu(float v) { return v > 0.f ? v : 0.2f * v; }

// ---------------- zero-init everything that gets atomically accumulated ----
__global__ void k_zero(float* __restrict__ out) {
    long i = blockIdx.x * (long)blockDim.x + threadIdx.x;
    long stride = (long)gridDim.x * blockDim.x;
    for (long j = i; j < (long)NN * 128; j += stride) g_out1[j] = 0.f;
    for (long j = i; j < (long)NN * 32; j += stride) out[j] = 0.f;
    for (long j = i; j < (long)NN * 4; j += stride) g_den1[j] = 0.f;
    for (long j = i; j < (long)NN; j += stride) g_den2[j] = 0.f;
}

// ---------------- GEMM1: [N,128] x [128,128] -> g_h1 -----------------------
// block = 32 rows x 128 cols, 256 threads; warp handles 4 rows, lane 4 cols.
__global__ __launch_bounds__(256) void k_gemm1(const float* __restrict__ x,
                                               const float* __restrict__ W) {
    __shared__ float xs[32][33];
    __shared__ __align__(16) float Ws[32 * 128];
    int tid = threadIdx.x;
    int lane = tid & 31, wid = tid >> 5;
    int row0 = blockIdx.x * 32;
    float4 acc[4];
#pragma unroll
    for (int r = 0; r < 4; r++) acc[r] = make_float4(0.f, 0.f, 0.f, 0.f);

    for (int kt = 0; kt < 4; kt++) {
#pragma unroll
        for (int i = 0; i < 4; i++) {
            int idx = tid + 256 * i;
            int r = idx >> 5, c = idx & 31;
            xs[r][c] = x[(long)(row0 + r) * 128 + kt * 32 + c];
        }
#pragma unroll
        for (int i = 0; i < 16; i++) {
            int idx = tid + 256 * i;
            int kr = idx >> 7, col = idx & 127;
            Ws[kr * 128 + col] = W[(kt * 32 + kr) * 128 + col];
        }
        __syncthreads();
#pragma unroll
        for (int kk = 0; kk < 32; kk++) {
            float4 wv = *(float4*)&Ws[kk * 128 + lane * 4];
#pragma unroll
            for (int r = 0; r < 4; r++) {
                float xv = xs[wid * 4 + r][kk];
                acc[r].x += xv * wv.x;
                acc[r].y += xv * wv.y;
                acc[r].z += xv * wv.z;
                acc[r].w += xv * wv.w;
            }
        }
        __syncthreads();
    }
#pragma unroll
    for (int r = 0; r < 4; r++)
        *(float4*)&g_h1[(long)(row0 + wid * 4 + r) * 128 + lane * 4] = acc[r];
}

// ---------------- GEMM2: [N,128] x [128,32] -> g_h2 ------------------------
// block = 32 rows, 128 threads; warp handles 8 rows, lane = col.
__global__ __launch_bounds__(128) void k_gemm2(const float* __restrict__ W) {
    __shared__ float xs[32][33];
    __shared__ float Ws[32 * 32];
    int tid = threadIdx.x, lane = tid & 31, wid = tid >> 5;
    int row0 = blockIdx.x * 32;
    float acc[8];
#pragma unroll
    for (int r = 0; r < 8; r++) acc[r] = 0.f;

    for (int kt = 0; kt < 4; kt++) {
#pragma unroll
        for (int i = 0; i < 8; i++) {
            int idx = tid + 128 * i;
            int r = idx >> 5, c = idx & 31;
            xs[r][c] = g_out1[(long)(row0 + r) * 128 + kt * 32 + c];
            Ws[idx] = W[(kt * 32 + r) * 32 + c];
        }
        __syncthreads();
#pragma unroll
        for (int kk = 0; kk < 32; kk++) {
            float wv = Ws[kk * 32 + lane];
#pragma unroll
            for (int r = 0; r < 8; r++) acc[r] += xs[wid * 8 + r][kk] * wv;
        }
        __syncthreads();
    }
#pragma unroll
    for (int r = 0; r < 8; r++)
        g_h2[(long)(row0 + wid * 8 + r) * 32 + lane] = acc[r];
}

// ---------------- attention coefficients, layer 1 (4 heads of 32) ----------
__global__ __launch_bounds__(128) void k_coef1(const float* __restrict__ a_src,
                                               const float* __restrict__ a_dst) {
    int wid = threadIdx.x >> 5, lane = threadIdx.x & 31;
    int n = blockIdx.x * 4 + wid;
    if (n >= NN) return;
    float ps[4], pd[4];
#pragma unroll
    for (int k = 0; k < 4; k++) {
        float hv = g_h1[(long)n * 128 + k * 32 + lane];
        ps[k] = hv * __ldg(&a_src[k * 32 + lane]);
        pd[k] = hv * __ldg(&a_dst[k * 32 + lane]);
    }
#pragma unroll
    for (int o = 16; o > 0; o >>= 1) {
#pragma unroll
        for (int k = 0; k < 4; k++) {
            ps[k] += __shfl_xor_sync(0xffffffffu, ps[k], o);
            pd[k] += __shfl_xor_sync(0xffffffffu, pd[k], o);
        }
    }
    if (lane == 0) {
#pragma unroll
        for (int k = 0; k < 4; k++) {
            g_as1[n * 4 + k] = ps[k];
            g_ad1[n * 4 + k] = pd[k];
        }
    }
}

// ---------------- attention coefficients, layer 2 (1 head of 32) -----------
__global__ __launch_bounds__(128) void k_coef2(const float* __restrict__ a_src,
                                               const float* __restrict__ a_dst) {
    int wid = threadIdx.x >> 5, lane = threadIdx.x & 31;
    int n = blockIdx.x * 4 + wid;
    if (n >= NN) return;
    float hv = g_h2[(long)n * 32 + lane];
    float ps = hv * __ldg(&a_src[lane]);
    float pd = hv * __ldg(&a_dst[lane]);
#pragma unroll
    for (int o = 16; o > 0; o >>= 1) {
        ps += __shfl_xor_sync(0xffffffffu, ps, o);
        pd += __shfl_xor_sync(0xffffffffu, pd, o);
    }
    if (lane == 0) {
        g_as2[n] = ps;
        g_ad2[n] = pd;
    }
}

// ---------------- edge pass B, layer 1: w = exp(lrelu(as+ad)), denom -------
// NOTE: inputs are tiny (|e| << 80), so softmax without max-subtraction is
// exactly equivalent mathematically and safe in fp32 here.
__global__ __launch_bounds__(256) void k_edgeB1(const int* __restrict__ ei) {
    int e = blockIdx.x * blockDim.x + threadIdx.x;
    if (e >= EN) return;
    int src, dst;
    if (e < EE) { src = ei[e]; dst = ei[EE + e]; }
    else { src = dst = e - EE; }
    float4 s = *(const float4*)&g_as1[src * 4];
    float4 d = *(const float4*)&g_ad1[dst * 4];
    float4 w;
    w.x = __expf(lrelu(s.x + d.x));
    w.y = __expf(lrelu(s.y + d.y));
    w.z = __expf(lrelu(s.z + d.z));
    w.w = __expf(lrelu(s.w + d.w));
    *(float4*)&g_w1[(long)e * 4] = w;
    atomicAdd(&g_den1[dst * 4 + 0], w.x);
    atomicAdd(&g_den1[dst * 4 + 1], w.y);
    atomicAdd(&g_den1[dst * 4 + 2], w.z);
    atomicAdd(&g_den1[dst * 4 + 3], w.w);
}

// ---------------- edge pass C, layer 1: warp-per-edge scatter-add ----------
__global__ __launch_bounds__(256) void k_edgeC1(const int* __restrict__ ei) {
    int widx = blockIdx.x * (blockDim.x >> 5) + (threadIdx.x >> 5);
    int lane = threadIdx.x & 31;
    if (widx >= EN) return;
    int src, dst;
    if (widx < EE) { src = ei[widx]; dst = ei[EE + widx]; }
    else { src = dst = widx - EE; }
    float4 w = *(const float4*)&g_w1[(long)widx * 4];
    float4 dn = *(const float4*)&g_den1[dst * 4];
    float a[4] = {w.x / dn.x, w.y / dn.y, w.z / dn.z, w.w / dn.w};
#pragma unroll
    for (int k = 0; k < 4; k++) {
        float v = __ldg(&g_h1[(long)src * 128 + k * 32 + lane]);
        atomicAdd(&g_out1[(long)dst * 128 + k * 32 + lane], a[k] * v);
    }
}

// ---------------- finalize layer 1: +b1, relu ------------------------------
__global__ void k_fin1(const float* __restrict__ b) {
    long i = blockIdx.x * (long)blockDim.x + threadIdx.x;
    long stride = (long)gridDim.x * blockDim.x;
    for (long j = i; j < (long)NN * 128; j += stride) {
        float v = g_out1[j] + __ldg(&b[j & 127]);
        g_out1[j] = v > 0.f ? v : 0.f;
    }
}

// ---------------- edge pass B, layer 2 -------------------------------------
__global__ __launch_bounds__(256) void k_edgeB2(const int* __restrict__ ei) {
    int e = blockIdx.x * blockDim.x + threadIdx.x;
    if (e >= EN) return;
    int src, dst;
    if (e < EE) { src = ei[e]; dst = ei[EE + e]; }
    else { src = dst = e - EE; }
    float w = __expf(lrelu(g_as2[src] + g_ad2[dst]));
    g_w2[e] = w;
    atomicAdd(&g_den2[dst], w);
}

// ---------------- edge pass C, layer 2: warp-per-edge, 32 channels ---------
__global__ __launch_bounds__(256) void k_edgeC2(const int* __restrict__ ei,
                                                float* __restrict__ out) {
    int widx = blockIdx.x * (blockDim.x >> 5) + (threadIdx.x >> 5);
    int lane = threadIdx.x & 31;
    if (widx >= EN) return;
    int src, dst;
    if (widx < EE) { src = ei[widx]; dst = ei[EE + widx]; }
    else { src = dst = widx - EE; }
    float a = g_w2[widx] / g_den2[dst];
    float v = __ldg(&g_h2[(long)src * 32 + lane]);
    atomicAdd(&out[(long)dst * 32 + lane], a * v);
}

// ---------------- finalize layer 2: +b2 ------------------------------------
__global__ void k_fin2(float* __restrict__ out, const float* __restrict__ b) {
    long i = blockIdx.x * (long)blockDim.x + threadIdx.x;
    long stride = (long)gridDim.x * blockDim.x;
    for (long j = i; j < (long)NN * 32; j += stride)
        out[j] += __ldg(&b[j & 31]);
}

// ---------------- launch ----------------------------------------------------
extern "C" void kernel_launch(void* const* d_in, const int* in_sizes, int n_in,
                              void* d_out, int out_size) {
    const float* x   = (const float*)d_in[0];
    const int*   ei  = (const int*)d_in[1];
    const float* W1  = (const float*)d_in[2];
    const float* as1 = (const float*)d_in[3];
    const float* ad1 = (const float*)d_in[4];
    const float* b1  = (const float*)d_in[5];
    const float* W2  = (const float*)d_in[6];
    const float* as2 = (const float*)d_in[7];
    const float* ad2 = (const float*)d_in[8];
    const float* b2  = (const float*)d_in[9];
    float* out = (float*)d_out;

    k_zero<<<4096, 256>>>(out);
    k_gemm1<<<NN / 32, 256>>>(x, W1);
    k_coef1<<<(NN + 3) / 4, 128>>>(as1, ad1);
    k_edgeB1<<<(EN + 255) / 256, 256>>>(ei);
    k_edgeC1<<<(EN + 7) / 8, 256>>>(ei);
    k_fin1<<<4096, 256>>>(b1);
    k_gemm2<<<NN / 32, 128>>>(W2);
    k_coef2<<<(NN + 3) / 4, 128>>>(as2, ad2);
    k_edgeB2<<<(EN + 255) / 256, 256>>>(ei);
    k_edgeC2<<<(EN + 7) / 8, 256>>>(ei, out);
    k_fin2<<<2048, 256>>>(out, b2);
}

// round 2
// speedup vs baseline: 2.0513x; 2.0513x over previous
#include <cuda_runtime.h>

#define NN 100000
#define EE 1600000
#define SCAN_NB 196   // ceil(NN/512)

// ---------------- scratch (device globals; no allocation allowed) ----------
__device__ float g_h1[NN * 128];    // conv1 linear output   (51.2 MB)
__device__ float g_out1[NN * 128];  // conv1 aggregated+relu (51.2 MB)
__device__ float g_h2[NN * 32];     // conv2 linear output   (12.8 MB)
__device__ float g_as1[NN * 4];
__device__ float g_ad1[NN * 4];
__device__ float g_as2[NN];
__device__ float g_ad2[NN];
__device__ int   g_cnt[NN];
__device__ int   g_off[NN + 1];
__device__ int   g_cur[NN];
__device__ int   g_part[SCAN_NB];
__device__ int   g_pofs[SCAN_NB];
__device__ int   g_srcs[EE];        // src ids sorted by dst (6.4 MB)

__device__ __forceinline__ float lrelu(float v) { return v > 0.f ? v : 0.2f * v; }

// ---------------- CSR build -------------------------------------------------
__global__ void k_zero_cnt() {
    int i = blockIdx.x * blockDim.x + threadIdx.x;
    if (i < NN) g_cnt[i] = 0;
}

__global__ __launch_bounds__(256) void k_hist(const int* __restrict__ ei) {
    int e = blockIdx.x * blockDim.x + threadIdx.x;
    if (e < EE) atomicAdd(&g_cnt[ei[EE + e]], 1);
}

__global__ __launch_bounds__(512) void k_scan1() {
    int i = blockIdx.x * 512 + threadIdx.x;
    int lane = threadIdx.x & 31, wid = threadIdx.x >> 5;
    int v = (i < NN) ? g_cnt[i] : 0;
    int x = v;
#pragma unroll
    for (int o = 1; o < 32; o <<= 1) {
        int t = __shfl_up_sync(0xffffffffu, x, o);
        if (lane >= o) x += t;
    }
    __shared__ int ws[16];
    if (lane == 31) ws[wid] = x;
    __syncthreads();
    if (wid == 0 && lane < 16) {
        int y = ws[lane];
#pragma unroll
        for (int o = 1; o < 16; o <<= 1) {
            int t = __shfl_up_sync(0xffffu, y, o);
            if (lane >= o) y += t;
        }
        ws[lane] = y;
    }
    __syncthreads();
    int incl = x + (wid > 0 ? ws[wid - 1] : 0);
    if (i < NN) g_off[i] = incl - v;          // exclusive (block-local)
    if (threadIdx.x == 511) g_part[blockIdx.x] = incl;
}

__global__ __launch_bounds__(256) void k_scan2() {
    int lane = threadIdx.x & 31, wid = threadIdx.x >> 5;
    int t = threadIdx.x;
    int v = (t < SCAN_NB) ? g_part[t] : 0;
    int x = v;
#pragma unroll
    for (int o = 1; o < 32; o <<= 1) {
        int u = __shfl_up_sync(0xffffffffu, x, o);
        if (lane >= o) x += u;
    }
    __shared__ int ws[8];
    if (lane == 31) ws[wid] = x;
    __syncthreads();
    if (wid == 0 && lane < 8) {
        int y = ws[lane];
#pragma unroll
        for (int o = 1; o < 8; o <<= 1) {
            int u = __shfl_up_sync(0xffu, y, o);
            if (lane >= o) y += u;
        }
        ws[lane] = y;
    }
    __syncthreads();
    int incl = x + (wid > 0 ? ws[wid - 1] : 0);
    if (t < SCAN_NB) g_pofs[t] = incl - v;    // exclusive block offsets
}

__global__ __launch_bounds__(512) void k_scan3() {
    int i = blockIdx.x * 512 + threadIdx.x;
    if (i < NN) {
        int o = g_off[i] + g_pofs[blockIdx.x];
        g_off[i] = o;
        g_cur[i] = o;
    }
    if (i == 0) g_off[NN] = EE;
}

__global__ __launch_bounds__(256) void k_scatter(const int* __restrict__ ei) {
    int e = blockIdx.x * blockDim.x + threadIdx.x;
    if (e >= EE) return;
    int dst = ei[EE + e];
    int pos = atomicAdd(&g_cur[dst], 1);
    g_srcs[pos] = ei[e];
}

// ---------------- GEMM1: [N,128] x [128,128] -> g_h1 -----------------------
__global__ __launch_bounds__(256) void k_gemm1(const float* __restrict__ x,
                                               const float* __restrict__ W) {
    __shared__ float xs[32][33];
    __shared__ __align__(16) float Ws[32 * 128];
    int tid = threadIdx.x;
    int lane = tid & 31, wid = tid >> 5;
    int row0 = blockIdx.x * 32;
    float4 acc[4];
#pragma unroll
    for (int r = 0; r < 4; r++) acc[r] = make_float4(0.f, 0.f, 0.f, 0.f);

    for (int kt = 0; kt < 4; kt++) {
#pragma unroll
        for (int i = 0; i < 4; i++) {
            int idx = tid + 256 * i;
            int r = idx >> 5, c = idx & 31;
            xs[r][c] = x[(long)(row0 + r) * 128 + kt * 32 + c];
        }
#pragma unroll
        for (int i = 0; i < 16; i++) {
            int idx = tid + 256 * i;
            int kr = idx >> 7, col = idx & 127;
            Ws[kr * 128 + col] = W[(kt * 32 + kr) * 128 + col];
        }
        __syncthreads();
#pragma unroll
        for (int kk = 0; kk < 32; kk++) {
            float4 wv = *(float4*)&Ws[kk * 128 + lane * 4];
#pragma unroll
            for (int r = 0; r < 4; r++) {
                float xv = xs[wid * 4 + r][kk];
                acc[r].x += xv * wv.x;
                acc[r].y += xv * wv.y;
                acc[r].z += xv * wv.z;
                acc[r].w += xv * wv.w;
            }
        }
        __syncthreads();
    }
#pragma unroll
    for (int r = 0; r < 4; r++)
        *(float4*)&g_h1[(long)(row0 + wid * 4 + r) * 128 + lane * 4] = acc[r];
}

// ---------------- GEMM2: [N,128] x [128,32] -> g_h2 ------------------------
__global__ __launch_bounds__(128) void k_gemm2(const float* __restrict__ W) {
    __shared__ float xs[32][33];
    __shared__ float Ws[32 * 32];
    int tid = threadIdx.x, lane = tid & 31, wid = tid >> 5;
    int row0 = blockIdx.x * 32;
    float acc[8];
#pragma unroll
    for (int r = 0; r < 8; r++) acc[r] = 0.f;

    for (int kt = 0; kt < 4; kt++) {
#pragma unroll
        for (int i = 0; i < 8; i++) {
            int idx = tid + 128 * i;
            int r = idx >> 5, c = idx & 31;
            xs[r][c] = g_out1[(long)(row0 + r) * 128 + kt * 32 + c];
            Ws[idx] = W[(kt * 32 + r) * 32 + c];
        }
        __syncthreads();
#pragma unroll
        for (int kk = 0; kk < 32; kk++) {
            float wv = Ws[kk * 32 + lane];
#pragma unroll
            for (int r = 0; r < 8; r++) acc[r] += xs[wid * 8 + r][kk] * wv;
        }
        __syncthreads();
    }
#pragma unroll
    for (int r = 0; r < 8; r++)
        g_h2[(long)(row0 + wid * 8 + r) * 32 + lane] = acc[r];
}

// ---------------- attention coefficients ------------------------------------
__global__ __launch_bounds__(128) void k_coef1(const float* __restrict__ a_src,
                                               const float* __restrict__ a_dst) {
    int wid = threadIdx.x >> 5, lane = threadIdx.x & 31;
    int n = blockIdx.x * 4 + wid;
    if (n >= NN) return;
    float ps[4], pd[4];
#pragma unroll
    for (int k = 0; k < 4; k++) {
        float hv = g_h1[(long)n * 128 + k * 32 + lane];
        ps[k] = hv * __ldg(&a_src[k * 32 + lane]);
        pd[k] = hv * __ldg(&a_dst[k * 32 + lane]);
    }
#pragma unroll
    for (int o = 16; o > 0; o >>= 1) {
#pragma unroll
        for (int k = 0; k < 4; k++) {
            ps[k] += __shfl_xor_sync(0xffffffffu, ps[k], o);
            pd[k] += __shfl_xor_sync(0xffffffffu, pd[k], o);
        }
    }
    if (lane == 0) {
#pragma unroll
        for (int k = 0; k < 4; k++) {
            g_as1[n * 4 + k] = ps[k];
            g_ad1[n * 4 + k] = pd[k];
        }
    }
}

__global__ __launch_bounds__(128) void k_coef2(const float* __restrict__ a_src,
                                               const float* __restrict__ a_dst) {
    int wid = threadIdx.x >> 5, lane = threadIdx.x & 31;
    int n = blockIdx.x * 4 + wid;
    if (n >= NN) return;
    float hv = g_h2[(long)n * 32 + lane];
    float ps = hv * __ldg(&a_src[lane]);
    float pd = hv * __ldg(&a_dst[lane]);
#pragma unroll
    for (int o = 16; o > 0; o >>= 1) {
        ps += __shfl_xor_sync(0xffffffffu, ps, o);
        pd += __shfl_xor_sync(0xffffffffu, pd, o);
    }
    if (lane == 0) {
        g_as2[n] = ps;
        g_ad2[n] = pd;
    }
}

// ---------------- layer-1 gather: warp per dst node -------------------------
// Softmax without max-subtraction: |e| << 80 (weights scaled 0.05), exact here.
__global__ __launch_bounds__(256) void k_gat1(const float* __restrict__ b) {
    int wid = threadIdx.x >> 5, lane = threadIdx.x & 31;
    int n = blockIdx.x * 8 + wid;
    if (n >= NN) return;
    int head = lane >> 3;
    float ad_l = (lane < 4) ? g_ad1[n * 4 + lane] : 0.f;

    // self loop
    float w4 = 0.f, den4 = 0.f;
    if (lane < 4) {
        w4 = __expf(lrelu(g_as1[n * 4 + lane] + ad_l));
        den4 = w4;
    }
    float w = __shfl_sync(0xffffffffu, w4, head);
    float4 hv = *(const float4*)&g_h1[(long)n * 128 + lane * 4];
    float4 acc;
    acc.x = w * hv.x; acc.y = w * hv.y; acc.z = w * hv.z; acc.w = w * hv.w;

    int beg = g_off[n], end = g_off[n + 1];
    for (int j = beg; j < end; j++) {
        int s = g_srcs[j];
        float wv = 0.f;
        if (lane < 4) {
            wv = __expf(lrelu(g_as1[s * 4 + lane] + ad_l));
            den4 += wv;
        }
        float ww = __shfl_sync(0xffffffffu, wv, head);
        float4 h = *(const float4*)&g_h1[(long)s * 128 + lane * 4];
        acc.x += ww * h.x; acc.y += ww * h.y; acc.z += ww * h.z; acc.w += ww * h.w;
    }
    float den = __shfl_sync(0xffffffffu, den4, head);
    float inv = 1.f / den;
    float4 bb = *(const float4*)&b[lane * 4];
    float4 o;
    o.x = fmaxf(acc.x * inv + bb.x, 0.f);
    o.y = fmaxf(acc.y * inv + bb.y, 0.f);
    o.z = fmaxf(acc.z * inv + bb.z, 0.f);
    o.w = fmaxf(acc.w * inv + bb.w, 0.f);
    *(float4*)&g_out1[(long)n * 128 + lane * 4] = o;
}

// ---------------- layer-2 gather: warp per dst node, 32 channels ------------
__global__ __launch_bounds__(256) void k_gat2(float* __restrict__ out,
                                              const float* __restrict__ b) {
    int wid = threadIdx.x >> 5, lane = threadIdx.x & 31;
    int n = blockIdx.x * 8 + wid;
    if (n >= NN) return;
    float adv = g_ad2[n];

    float w0 = 0.f, den = 0.f;
    if (lane == 0) {
        w0 = __expf(lrelu(g_as2[n] + adv));
        den = w0;
    }
    float w = __shfl_sync(0xffffffffu, w0, 0);
    float acc = w * g_h2[(long)n * 32 + lane];

    int beg = g_off[n], end = g_off[n + 1];
    for (int j = beg; j < end; j++) {
        int s = g_srcs[j];
        float wv = 0.f;
        if (lane == 0) {
            wv = __expf(lrelu(g_as2[s] + adv));
            den += wv;
        }
        float ww = __shfl_sync(0xffffffffu, wv, 0);
        acc += ww * g_h2[(long)s * 32 + lane];
    }
    float d = __shfl_sync(0xffffffffu, den, 0);
    out[(long)n * 32 + lane] = acc / d + __ldg(&b[lane]);
}

// ---------------- launch ----------------------------------------------------
extern "C" void kernel_launch(void* const* d_in, const int* in_sizes, int n_in,
                              void* d_out, int out_size) {
    const float* x   = (const float*)d_in[0];
    const int*   ei  = (const int*)d_in[1];
    const float* W1  = (const float*)d_in[2];
    const float* as1 = (const float*)d_in[3];
    const float* ad1 = (const float*)d_in[4];
    const float* b1  = (const float*)d_in[5];
    const float* W2  = (const float*)d_in[6];
    const float* as2 = (const float*)d_in[7];
    const float* ad2 = (const float*)d_in[8];
    const float* b2  = (const float*)d_in[9];
    float* out = (float*)d_out;

    // CSR build (overlaps with gemm1 on separate data)
    k_zero_cnt<<<(NN + 255) / 256, 256>>>();
    k_hist<<<(EE + 255) / 256, 256>>>(ei);
    k_gemm1<<<NN / 32, 256>>>(x, W1);
    k_scan1<<<SCAN_NB, 512>>>();
    k_scan2<<<1, 256>>>();
    k_scan3<<<SCAN_NB, 512>>>();
    k_scatter<<<(EE + 255) / 256, 256>>>(ei);
    k_coef1<<<(NN + 3) / 4, 128>>>(as1, ad1);
    k_gat1<<<(NN + 7) / 8, 256>>>(b1);
    k_gemm2<<<NN / 32, 128>>>(W2);
    k_coef2<<<(NN + 3) / 4, 128>>>(as2, ad2);
    k_gat2<<<(NN + 7) / 8, 256>>>(out, b2);
}

// round 4
// speedup vs baseline: 2.0850x; 1.0164x over previous
#include <cuda_runtime.h>

#define NN 100000
#define EE 1600000
#define SCAN_NB 196   // ceil(NN/512)

typedef unsigned long long ull;

// ---------------- scratch (device globals; no allocation allowed) ----------
__device__ float g_h1[NN * 128];    // conv1 linear output   (51.2 MB)
__device__ float g_out1[NN * 128];  // conv1 aggregated+relu (51.2 MB)
__device__ float g_h2[NN * 32];     // conv2 linear output   (12.8 MB)
__device__ float g_as1[NN * 4];
__device__ float g_ad1[NN * 4];
__device__ float g_as2[NN];
__device__ float g_ad2[NN];
__device__ int   g_cnt[NN];
__device__ int   g_off[NN + 1];
__device__ int   g_cur[NN];
__device__ int   g_part[SCAN_NB];
__device__ int   g_pofs[SCAN_NB];
__device__ int   g_srcs[EE];        // src ids sorted by dst (6.4 MB)

__device__ __forceinline__ float lrelu(float v) { return v > 0.f ? v : 0.2f * v; }

// packed fp32x2 helpers (sm_100+ only; doubles fp32 FMA throughput per slot)
__device__ __forceinline__ void fma2(ull& d, ull a, ull b) {
    asm("fma.rn.f32x2 %0, %1, %2, %0;" : "+l"(d) : "l"(a), "l"(b));
}
__device__ __forceinline__ ull pack2(float lo, float hi) {
    ull r;
    asm("mov.b64 %0, {%1, %2};" : "=l"(r) : "f"(lo), "f"(hi));
    return r;
}
__device__ __forceinline__ float2 unpack2(ull v) {
    float2 r;
    asm("mov.b64 {%0, %1}, %2;" : "=f"(r.x), "=f"(r.y) : "l"(v));
    return r;
}

// ---------------- CSR build -------------------------------------------------
__global__ void k_zero_cnt() {
    int i = blockIdx.x * blockDim.x + threadIdx.x;
    if (i < NN) g_cnt[i] = 0;
}

__global__ __launch_bounds__(256) void k_hist(const int* __restrict__ ei) {
    int e = blockIdx.x * blockDim.x + threadIdx.x;
    if (e < EE) atomicAdd(&g_cnt[ei[EE + e]], 1);
}

__global__ __launch_bounds__(512) void k_scan1() {
    int i = blockIdx.x * 512 + threadIdx.x;
    int lane = threadIdx.x & 31, wid = threadIdx.x >> 5;
    int v = (i < NN) ? g_cnt[i] : 0;
    int x = v;
#pragma unroll
    for (int o = 1; o < 32; o <<= 1) {
        int t = __shfl_up_sync(0xffffffffu, x, o);
        if (lane >= o) x += t;
    }
    __shared__ int ws[16];
    if (lane == 31) ws[wid] = x;
    __syncthreads();
    if (wid == 0 && lane < 16) {
        int y = ws[lane];
#pragma unroll
        for (int o = 1; o < 16; o <<= 1) {
            int t = __shfl_up_sync(0xffffu, y, o);
            if (lane >= o) y += t;
        }
        ws[lane] = y;
    }
    __syncthreads();
    int incl = x + (wid > 0 ? ws[wid - 1] : 0);
    if (i < NN) g_off[i] = incl - v;
    if (threadIdx.x == 511) g_part[blockIdx.x] = incl;
}

__global__ __launch_bounds__(256) void k_scan2() {
    int lane = threadIdx.x & 31, wid = threadIdx.x >> 5;
    int t = threadIdx.x;
    int v = (t < SCAN_NB) ? g_part[t] : 0;
    int x = v;
#pragma unroll
    for (int o = 1; o < 32; o <<= 1) {
        int u = __shfl_up_sync(0xffffffffu, x, o);
        if (lane >= o) x += u;
    }
    __shared__ int ws[8];
    if (lane == 31) ws[wid] = x;
    __syncthreads();
    if (wid == 0 && lane < 8) {
        int y = ws[lane];
#pragma unroll
        for (int o = 1; o < 8; o <<= 1) {
            int u = __shfl_up_sync(0xffu, y, o);
            if (lane >= o) y += u;
        }
        ws[lane] = y;
    }
    __syncthreads();
    int incl = x + (wid > 0 ? ws[wid - 1] : 0);
    if (t < SCAN_NB) g_pofs[t] = incl - v;
}

__global__ __launch_bounds__(512) void k_scan3() {
    int i = blockIdx.x * 512 + threadIdx.x;
    if (i < NN) {
        int o = g_off[i] + g_pofs[blockIdx.x];
        g_off[i] = o;
        g_cur[i] = o;
    }
    if (i == 0) g_off[NN] = EE;
}

__global__ __launch_bounds__(256) void k_scatter(const int* __restrict__ ei) {
    int e = blockIdx.x * blockDim.x + threadIdx.x;
    if (e >= EE) return;
    int dst = ei[EE + e];
    int pos = atomicAdd(&g_cur[dst], 1);
    g_srcs[pos] = ei[e];
}

// ---------------- GEMM1: [N,128] x [128,128] -> g_h1, f32x2 ----------------
// 256 threads, tile 64 rows x 128 cols. Warp w -> rows [w*8, w*8+8),
// lane -> col quad lane*4. Thread: 8 rows (4 pairs) x 4 cols = 16 f32x2 accs.
__global__ __launch_bounds__(256) void k_gemm1(const float* __restrict__ x,
                                               const float* __restrict__ W) {
    __shared__ float xs[32][66];                 // [k][row], transposed, pad 2
    __shared__ __align__(16) float Ws[32][128];
    int tid = threadIdx.x, lane = tid & 31, wid = tid >> 5;
    int row0 = blockIdx.x * 64;
    int rbase = wid * 8;
    int cq = lane * 4;
    ull acc[4][4];
#pragma unroll
    for (int p = 0; p < 4; p++)
#pragma unroll
        for (int c = 0; c < 4; c++) acc[p][c] = 0ULL;

    for (int kt = 0; kt < 4; kt++) {
#pragma unroll
        for (int i = 0; i < 8; i++) {           // x tile: 64x32, transposed store
            int idx = tid + 256 * i;
            int c = idx & 31, r = idx >> 5;
            int gr = row0 + r;
            xs[c][r] = (gr < NN) ? x[(long)gr * 128 + kt * 32 + c] : 0.f;
        }
#pragma unroll
        for (int i = 0; i < 16; i++) {          // W tile: 32x128
            int idx = tid + 256 * i;
            int col = idx & 127, kr = idx >> 7;
            Ws[kr][col] = W[(kt * 32 + kr) * 128 + col];
        }
        __syncthreads();
#pragma unroll
        for (int kk = 0; kk < 32; kk++) {
            ull a0 = *(const ull*)&xs[kk][rbase + 0];
            ull a1 = *(const ull*)&xs[kk][rbase + 2];
            ull a2 = *(const ull*)&xs[kk][rbase + 4];
            ull a3 = *(const ull*)&xs[kk][rbase + 6];
            float4 wv = *(const float4*)&Ws[kk][cq];
            ull b0 = pack2(wv.x, wv.x);
            ull b1 = pack2(wv.y, wv.y);
            ull b2 = pack2(wv.z, wv.z);
            ull b3 = pack2(wv.w, wv.w);
            fma2(acc[0][0], a0, b0); fma2(acc[0][1], a0, b1);
            fma2(acc[0][2], a0, b2); fma2(acc[0][3], a0, b3);
            fma2(acc[1][0], a1, b0); fma2(acc[1][1], a1, b1);
            fma2(acc[1][2], a1, b2); fma2(acc[1][3], a1, b3);
            fma2(acc[2][0], a2, b0); fma2(acc[2][1], a2, b1);
            fma2(acc[2][2], a2, b2); fma2(acc[2][3], a2, b3);
            fma2(acc[3][0], a3, b0); fma2(acc[3][1], a3, b1);
            fma2(acc[3][2], a3, b2); fma2(acc[3][3], a3, b3);
        }
        __syncthreads();
    }
#pragma unroll
    for (int p = 0; p < 4; p++) {
        float2 u0 = unpack2(acc[p][0]), u1 = unpack2(acc[p][1]);
        float2 u2 = unpack2(acc[p][2]), u3 = unpack2(acc[p][3]);
        int gr = row0 + rbase + 2 * p;
        if (gr < NN)
            *(float4*)&g_h1[(long)gr * 128 + cq] = make_float4(u0.x, u1.x, u2.x, u3.x);
        if (gr + 1 < NN)
            *(float4*)&g_h1[(long)(gr + 1) * 128 + cq] = make_float4(u0.y, u1.y, u2.y, u3.y);
    }
}

// ---------------- GEMM2: [N,128] x [128,32] -> g_h2, f32x2 ------------------
// 128 threads, tile 128 rows x 32 cols. Warp w -> rows [w*32, w*32+32),
// lane>>3 -> row subgroup (8 rows), (lane&7)*4 -> col quad.
__global__ __launch_bounds__(128) void k_gemm2(const float* __restrict__ W) {
    __shared__ float xs[32][130];                // [k][row], pad 2
    __shared__ __align__(16) float Ws[32][32];
    int tid = threadIdx.x, lane = tid & 31, wid = tid >> 5;
    int row0 = blockIdx.x * 128;
    int rbase = wid * 32 + (lane >> 3) * 8;
    int cq = (lane & 7) * 4;
    ull acc[4][4];
#pragma unroll
    for (int p = 0; p < 4; p++)
#pragma unroll
        for (int c = 0; c < 4; c++) acc[p][c] = 0ULL;

    for (int kt = 0; kt < 4; kt++) {
#pragma unroll
        for (int i = 0; i < 32; i++) {          // 128x32 tile transposed
            int idx = tid + 128 * i;
            int c = idx & 31, r = idx >> 5;
            int gr = row0 + r;
            xs[c][r] = (gr < NN) ? g_out1[(long)gr * 128 + kt * 32 + c] : 0.f;
        }
#pragma unroll
        for (int i = 0; i < 8; i++) {           // W tile 32x32
            int idx = tid + 128 * i;
            int c = idx & 31, kr = idx >> 5;
            Ws[kr][c] = W[(kt * 32 + kr) * 32 + c];
        }
        __syncthreads();
#pragma unroll
        for (int kk = 0; kk < 32; kk++) {
            ull a0 = *(const ull*)&xs[kk][rbase + 0];
            ull a1 = *(const ull*)&xs[kk][rbase + 2];
            ull a2 = *(const ull*)&xs[kk][rbase + 4];
            ull a3 = *(const ull*)&xs[kk][rbase + 6];
            float4 wv = *(const float4*)&Ws[kk][cq];
            ull b0 = pack2(wv.x, wv.x);
            ull b1 = pack2(wv.y, wv.y);
            ull b2 = pack2(wv.z, wv.z);
            ull b3 = pack2(wv.w, wv.w);
            fma2(acc[0][0], a0, b0); fma2(acc[0][1], a0, b1);
            fma2(acc[0][2], a0, b2); fma2(acc[0][3], a0, b3);
            fma2(acc[1][0], a1, b0); fma2(acc[1][1], a1, b1);
            fma2(acc[1][2], a1, b2); fma2(acc[1][3], a1, b3);
            fma2(acc[2][0], a2, b0); fma2(acc[2][1], a2, b1);
            fma2(acc[2][2], a2, b2); fma2(acc[2][3], a2, b3);
            fma2(acc[3][0], a3, b0); fma2(acc[3][1], a3, b1);
            fma2(acc[3][2], a3, b2); fma2(acc[3][3], a3, b3);
        }
        __syncthreads();
    }
#pragma unroll
    for (int p = 0; p < 4; p++) {
        float2 u0 = unpack2(acc[p][0]), u1 = unpack2(acc[p][1]);
        float2 u2 = unpack2(acc[p][2]), u3 = unpack2(acc[p][3]);
        int gr = row0 + rbase + 2 * p;
        if (gr < NN)
            *(float4*)&g_h2[(long)gr * 32 + cq] = make_float4(u0.x, u1.x, u2.x, u3.x);
        if (gr + 1 < NN)
            *(float4*)&g_h2[(long)(gr + 1) * 32 + cq] = make_float4(u0.y, u1.y, u2.y, u3.y);
    }
}

// ---------------- attention coefficients ------------------------------------
__global__ __launch_bounds__(128) void k_coef1(const float* __restrict__ a_src,
                                               const float* __restrict__ a_dst) {
    int wid = threadIdx.x >> 5, lane = threadIdx.x & 31;
    int n = blockIdx.x * 4 + wid;
    if (n >= NN) return;
    float ps[4], pd[4];
#pragma unroll
    for (int k = 0; k < 4; k++) {
        float hv = g_h1[(long)n * 128 + k * 32 + lane];
        ps[k] = hv * __ldg(&a_src[k * 32 + lane]);
        pd[k] = hv * __ldg(&a_dst[k * 32 + lane]);
    }
#pragma unroll
    for (int o = 16; o > 0; o >>= 1) {
#pragma unroll
        for (int k = 0; k < 4; k++) {
            ps[k] += __shfl_xor_sync(0xffffffffu, ps[k], o);
            pd[k] += __shfl_xor_sync(0xffffffffu, pd[k], o);
        }
    }
    if (lane == 0) {
#pragma unroll
        for (int k = 0; k < 4; k++) {
            g_as1[n * 4 + k] = ps[k];
            g_ad1[n * 4 + k] = pd[k];
        }
    }
}

__global__ __launch_bounds__(128) void k_coef2(const float* __restrict__ a_src,
                                               const float* __restrict__ a_dst) {
    int wid = threadIdx.x >> 5, lane = threadIdx.x & 31;
    int n = blockIdx.x * 4 + wid;
    if (n >= NN) return;
    float hv = g_h2[(long)n * 32 + lane];
    float ps = hv * __ldg(&a_src[lane]);
    float pd = hv * __ldg(&a_dst[lane]);
#pragma unroll
    for (int o = 16; o > 0; o >>= 1) {
        ps += __shfl_xor_sync(0xffffffffu, ps, o);
        pd += __shfl_xor_sync(0xffffffffu, pd, o);
    }
    if (lane == 0) {
        g_as2[n] = ps;
        g_ad2[n] = pd;
    }
}

// ---------------- layer-1 gather: warp per dst node, unroll x4 --------------
// Softmax without max-subtraction: |e| << 80 (weights scaled 0.05), exact here.
__global__ __launch_bounds__(256) void k_gat1(const float* __restrict__ b) {
    int wid = threadIdx.x >> 5, lane = threadIdx.x & 31;
    int n = blockIdx.x * 8 + wid;
    if (n >= NN) return;
    int head = lane >> 3;
    float ad_l = (lane < 4) ? g_ad1[n * 4 + lane] : 0.f;

    // self loop
    float w4 = 0.f, den4 = 0.f;
    if (lane < 4) {
        w4 = __expf(lrelu(g_as1[n * 4 + lane] + ad_l));
        den4 = w4;
    }
    float w = __shfl_sync(0xffffffffu, w4, head);
    float4 hv = *(const float4*)&g_h1[(long)n * 128 + lane * 4];
    float4 acc;
    acc.x = w * hv.x; acc.y = w * hv.y; acc.z = w * hv.z; acc.w = w * hv.w;

    int beg = g_off[n], end = g_off[n + 1];
    int j = beg;
    for (; j + 4 <= end; j += 4) {
        int s0 = __ldg(&g_srcs[j + 0]);
        int s1 = __ldg(&g_srcs[j + 1]);
        int s2 = __ldg(&g_srcs[j + 2]);
        int s3 = __ldg(&g_srcs[j + 3]);
        float4 h0 = *(const float4*)&g_h1[(long)s0 * 128 + lane * 4];
        float4 h1 = *(const float4*)&g_h1[(long)s1 * 128 + lane * 4];
        float4 h2 = *(const float4*)&g_h1[(long)s2 * 128 + lane * 4];
        float4 h3 = *(const float4*)&g_h1[(long)s3 * 128 + lane * 4];
        float w0 = 0.f, w1 = 0.f, w2 = 0.f, w3 = 0.f;
        if (lane < 4) {
            w0 = __expf(lrelu(__ldg(&g_as1[s0 * 4 + lane]) + ad_l));
            w1 = __expf(lrelu(__ldg(&g_as1[s1 * 4 + lane]) + ad_l));
            w2 = __expf(lrelu(__ldg(&g_as1[s2 * 4 + lane]) + ad_l));
            w3 = __expf(lrelu(__ldg(&g_as1[s3 * 4 + lane]) + ad_l));
            den4 += (w0 + w1) + (w2 + w3);
        }
        float ww0 = __shfl_sync(0xffffffffu, w0, head);
        float ww1 = __shfl_sync(0xffffffffu, w1, head);
        float ww2 = __shfl_sync(0xffffffffu, w2, head);
        float ww3 = __shfl_sync(0xffffffffu, w3, head);
        acc.x += ww0 * h0.x + ww1 * h1.x + ww2 * h2.x + ww3 * h3.x;
        acc.y += ww0 * h0.y + ww1 * h1.y + ww2 * h2.y + ww3 * h3.y;
        acc.z += ww0 * h0.z + ww1 * h1.z + ww2 * h2.z + ww3 * h3.z;
        acc.w += ww0 * h0.w + ww1 * h1.w + ww2 * h2.w + ww3 * h3.w;
    }
    for (; j < end; j++) {
        int s = __ldg(&g_srcs[j]);
        float wv = 0.f;
        if (lane < 4) {
            wv = __expf(lrelu(__ldg(&g_as1[s * 4 + lane]) + ad_l));
            den4 += wv;
        }
        float ww = __shfl_sync(0xffffffffu, wv, head);
        float4 h = *(const float4*)&g_h1[(long)s * 128 + lane * 4];
        acc.x += ww * h.x; acc.y += ww * h.y; acc.z += ww * h.z; acc.w += ww * h.w;
    }
    float den = __shfl_sync(0xffffffffu, den4, head);
    float inv = 1.f / den;
    float4 bb = *(const float4*)&b[lane * 4];
    float4 o;
    o.x = fmaxf(acc.x * inv + bb.x, 0.f);
    o.y = fmaxf(acc.y * inv + bb.y, 0.f);
    o.z = fmaxf(acc.z * inv + bb.z, 0.f);
    o.w = fmaxf(acc.w * inv + bb.w, 0.f);
    *(float4*)&g_out1[(long)n * 128 + lane * 4] = o;
}

// ---------------- layer-2 gather: warp per dst node, unroll x4 --------------
__global__ __launch_bounds__(256) void k_gat2(float* __restrict__ out,
                                              const float* __restrict__ b) {
    int wid = threadIdx.x >> 5, lane = threadIdx.x & 31;
    int n = blockIdx.x * 8 + wid;
    if (n >= NN) return;
    float adv = g_ad2[n];

    float w0s = 0.f, den = 0.f;
    if (lane == 0) {
        w0s = __expf(lrelu(g_as2[n] + adv));
        den = w0s;
    }
    float w = __shfl_sync(0xffffffffu, w0s, 0);
    float acc = w * g_h2[(long)n * 32 + lane];

    int beg = g_off[n], end = g_off[n + 1];
    int j = beg;
    for (; j + 4 <= end; j += 4) {
        int s0 = __ldg(&g_srcs[j + 0]);
        int s1 = __ldg(&g_srcs[j + 1]);
        int s2 = __ldg(&g_srcs[j + 2]);
        int s3 = __ldg(&g_srcs[j + 3]);
        float h0 = __ldg(&g_h2[(long)s0 * 32 + lane]);
        float h1 = __ldg(&g_h2[(long)s1 * 32 + lane]);
        float h2 = __ldg(&g_h2[(long)s2 * 32 + lane]);
        float h3 = __ldg(&g_h2[(long)s3 * 32 + lane]);
        float w0 = 0.f, w1 = 0.f, w2 = 0.f, w3 = 0.f;
        if (lane < 4) {
            int ss = (lane == 0) ? s0 : (lane == 1) ? s1 : (lane == 2) ? s2 : s3;
            float e = __expf(lrelu(__ldg(&g_as2[ss]) + adv));
            w0 = e;  // lane k holds weight for edge k
        }
        float ww0 = __shfl_sync(0xffffffffu, w0, 0);
        float ww1 = __shfl_sync(0xffffffffu, w0, 1);
        float ww2 = __shfl_sync(0xffffffffu, w0, 2);
        float ww3 = __shfl_sync(0xffffffffu, w0, 3);
        if (lane == 0) den += (ww0 + ww1) + (ww2 + ww3);
        acc += ww0 * h0 + ww1 * h1 + ww2 * h2 + ww3 * h3;
    }
    for (; j < end; j++) {
        int s = __ldg(&g_srcs[j]);
        float wv = 0.f;
        if (lane == 0) {
            wv = __expf(lrelu(__ldg(&g_as2[s]) + adv));
            den += wv;
        }
        float ww = __shfl_sync(0xffffffffu, wv, 0);
        acc += ww * __ldg(&g_h2[(long)s * 32 + lane]);
    }
    float d = __shfl_sync(0xffffffffu, den, 0);
    out[(long)n * 32 + lane] = acc / d + __ldg(&b[lane]);
}

// ---------------- launch ----------------------------------------------------
extern "C" void kernel_launch(void* const* d_in, const int* in_sizes, int n_in,
                              void* d_out, int out_size) {
    const float* x   = (const float*)d_in[0];
    const int*   ei  = (const int*)d_in[1];
    const float* W1  = (const float*)d_in[2];
    const float* as1 = (const float*)d_in[3];
    const float* ad1 = (const float*)d_in[4];
    const float* b1  = (const float*)d_in[5];
    const float* W2  = (const float*)d_in[6];
    const float* as2 = (const float*)d_in[7];
    const float* ad2 = (const float*)d_in[8];
    const float* b2  = (const float*)d_in[9];
    float* out = (float*)d_out;

    k_zero_cnt<<<(NN + 255) / 256, 256>>>();
    k_hist<<<(EE + 255) / 256, 256>>>(ei);
    k_gemm1<<<(NN + 63) / 64, 256>>>(x, W1);
    k_scan1<<<SCAN_NB, 512>>>();
    k_scan2<<<1, 256>>>();
    k_scan3<<<SCAN_NB, 512>>>();
    k_scatter<<<(EE + 255) / 256, 256>>>(ei);
    k_coef1<<<(NN + 3) / 4, 128>>>(as1, ad1);
    k_gat1<<<(NN + 7) / 8, 256>>>(b1);
    k_gemm2<<<(NN + 127) / 128, 128>>>(W2);
    k_coef2<<<(NN + 3) / 4, 128>>>(as2, ad2);
    k_gat2<<<(NN + 7) / 8, 256>>>(out, b2);
}

// round 13
// speedup vs baseline: 2.2873x; 1.0970x over previous
#include <cuda_runtime.h>
#include <cuda_fp16.h>

#define NN 100000
#define EE 1600000
#define SCAN_NB 196   // ceil(NN/512)

typedef unsigned long long ull;

// ---------------- scratch (device globals; no allocation allowed) ----------
__device__ __half g_h1h[NN * 128];   // conv1 linear out, fp16 (25.6 MB)
__device__ float  g_out1[NN * 128];  // conv1 aggregated+relu (51.2 MB)
__device__ __half g_h2h[NN * 32];    // conv2 linear out, fp16 (6.4 MB)
__device__ float g_as1[NN * 4];
__device__ float g_ad1[NN * 4];
__device__ float g_as2[NN];
__device__ float g_ad2[NN];
__device__ int   g_cnt[NN];
__device__ int   g_off[NN + 1];
__device__ int   g_cur[NN];
__device__ int   g_part[SCAN_NB];
__device__ int   g_pofs[SCAN_NB];
__device__ int   g_srcs[EE];         // src ids sorted by dst (6.4 MB)

__device__ __forceinline__ float lrelu(float v) { return v > 0.f ? v : 0.2f * v; }

// packed fp32x2 helpers
__device__ __forceinline__ void fma2(ull& d, ull a, ull b) {
    asm("fma.rn.f32x2 %0, %1, %2, %0;" : "+l"(d) : "l"(a), "l"(b));
}
__device__ __forceinline__ ull pack2(float lo, float hi) {
    ull r;
    asm("mov.b64 %0, {%1, %2};" : "=l"(r) : "f"(lo), "f"(hi));
    return r;
}
__device__ __forceinline__ float2 unpack2(ull v) {
    float2 r;
    asm("mov.b64 {%0, %1}, %2;" : "=f"(r.x), "=f"(r.y) : "l"(v));
    return r;
}

// fp16 pack/unpack of 4 channels
__device__ __forceinline__ uint2 f4_to_h4(float4 v) {
    __half2 lo = __floats2half2_rn(v.x, v.y);
    __half2 hi = __floats2half2_rn(v.z, v.w);
    uint2 r;
    r.x = *(unsigned*)&lo;
    r.y = *(unsigned*)&hi;
    return r;
}
__device__ __forceinline__ float4 h4_to_f4(uint2 u) {
    __half2 lo = *(__half2*)&u.x;
    __half2 hi = *(__half2*)&u.y;
    float2 a = __half22float2(lo);
    float2 b = __half22float2(hi);
    return make_float4(a.x, a.y, b.x, b.y);
}

// ---------------- CSR build -------------------------------------------------
__global__ void k_zero_cnt() {
    int i = blockIdx.x * blockDim.x + threadIdx.x;
    if (i < NN) g_cnt[i] = 0;
}

__global__ __launch_bounds__(256) void k_hist(const int* __restrict__ ei) {
    int e = blockIdx.x * blockDim.x + threadIdx.x;
    if (e < EE) atomicAdd(&g_cnt[ei[EE + e]], 1);
}

__global__ __launch_bounds__(512) void k_scan1() {
    int i = blockIdx.x * 512 + threadIdx.x;
    int lane = threadIdx.x & 31, wid = threadIdx.x >> 5;
    int v = (i < NN) ? g_cnt[i] : 0;
    int x = v;
#pragma unroll
    for (int o = 1; o < 32; o <<= 1) {
        int t = __shfl_up_sync(0xffffffffu, x, o);
        if (lane >= o) x += t;
    }
    __shared__ int ws[16];
    if (lane == 31) ws[wid] = x;
    __syncthreads();
    if (wid == 0 && lane < 16) {
        int y = ws[lane];
#pragma unroll
        for (int o = 1; o < 16; o <<= 1) {
            int t = __shfl_up_sync(0xffffu, y, o);
            if (lane >= o) y += t;
        }
        ws[lane] = y;
    }
    __syncthreads();
    int incl = x + (wid > 0 ? ws[wid - 1] : 0);
    if (i < NN) g_off[i] = incl - v;
    if (threadIdx.x == 511) g_part[blockIdx.x] = incl;
}

__global__ __launch_bounds__(256) void k_scan2() {
    int lane = threadIdx.x & 31, wid = threadIdx.x >> 5;
    int t = threadIdx.x;
    int v = (t < SCAN_NB) ? g_part[t] : 0;
    int x = v;
#pragma unroll
    for (int o = 1; o < 32; o <<= 1) {
        int u = __shfl_up_sync(0xffffffffu, x, o);
        if (lane >= o) x += u;
    }
    __shared__ int ws[8];
    if (lane == 31) ws[wid] = x;
    __syncthreads();
    if (wid == 0 && lane < 8) {
        int y = ws[lane];
#pragma unroll
        for (int o = 1; o < 8; o <<= 1) {
            int u = __shfl_up_sync(0xffu, y, o);
            if (lane >= o) y += u;
        }
        ws[lane] = y;
    }
    __syncthreads();
    int incl = x + (wid > 0 ? ws[wid - 1] : 0);
    if (t < SCAN_NB) g_pofs[t] = incl - v;
}

__global__ __launch_bounds__(512) void k_scan3() {
    int i = blockIdx.x * 512 + threadIdx.x;
    if (i < NN) {
        int o = g_off[i] + g_pofs[blockIdx.x];
        g_off[i] = o;
        g_cur[i] = o;
    }
    if (i == 0) g_off[NN] = EE;
}

__global__ __launch_bounds__(256) void k_scatter(const int* __restrict__ ei) {
    int e = blockIdx.x * blockDim.x + threadIdx.x;
    if (e >= EE) return;
    int dst = ei[EE + e];
    int pos = atomicAdd(&g_cur[dst], 1);
    g_srcs[pos] = ei[e];
}

// ---------------- GEMM1: [N,128] x [128,128] -> g_h1h (fp16) ---------------
__global__ __launch_bounds__(256) void k_gemm1(const float* __restrict__ x,
                                               const float* __restrict__ W) {
    __shared__ float xs[32][66];                 // [k][row], transposed, pad 2
    __shared__ __align__(16) float Ws[32][128];
    int tid = threadIdx.x, lane = tid & 31, wid = tid >> 5;
    int row0 = blockIdx.x * 64;
    int rbase = wid * 8;
    int cq = lane * 4;
    ull acc[4][4];
#pragma unroll
    for (int p = 0; p < 4; p++)
#pragma unroll
        for (int c = 0; c < 4; c++) acc[p][c] = 0ULL;

    for (int kt = 0; kt < 4; kt++) {
#pragma unroll
        for (int i = 0; i < 8; i++) {
            int idx = tid + 256 * i;
            int c = idx & 31, r = idx >> 5;
            int gr = row0 + r;
            xs[c][r] = (gr < NN) ? x[(long)gr * 128 + kt * 32 + c] : 0.f;
        }
#pragma unroll
        for (int i = 0; i < 16; i++) {
            int idx = tid + 256 * i;
            int col = idx & 127, kr = idx >> 7;
            Ws[kr][col] = W[(kt * 32 + kr) * 128 + col];
        }
        __syncthreads();
#pragma unroll
        for (int kk = 0; kk < 32; kk++) {
            ull a0 = *(const ull*)&xs[kk][rbase + 0];
            ull a1 = *(const ull*)&xs[kk][rbase + 2];
            ull a2 = *(const ull*)&xs[kk][rbase + 4];
            ull a3 = *(const ull*)&xs[kk][rbase + 6];
            float4 wv = *(const float4*)&Ws[kk][cq];
            ull b0 = pack2(wv.x, wv.x);
            ull b1 = pack2(wv.y, wv.y);
            ull b2 = pack2(wv.z, wv.z);
            ull b3 = pack2(wv.w, wv.w);
            fma2(acc[0][0], a0, b0); fma2(acc[0][1], a0, b1);
            fma2(acc[0][2], a0, b2); fma2(acc[0][3], a0, b3);
            fma2(acc[1][0], a1, b0); fma2(acc[1][1], a1, b1);
            fma2(acc[1][2], a1, b2); fma2(acc[1][3], a1, b3);
            fma2(acc[2][0], a2, b0); fma2(acc[2][1], a2, b1);
            fma2(acc[2][2], a2, b2); fma2(acc[2][3], a2, b3);
            fma2(acc[3][0], a3, b0); fma2(acc[3][1], a3, b1);
            fma2(acc[3][2], a3, b2); fma2(acc[3][3], a3, b3);
        }
        __syncthreads();
    }
#pragma unroll
    for (int p = 0; p < 4; p++) {
        float2 u0 = unpack2(acc[p][0]), u1 = unpack2(acc[p][1]);
        float2 u2 = unpack2(acc[p][2]), u3 = unpack2(acc[p][3]);
        int gr = row0 + rbase + 2 * p;
        if (gr < NN)
            *(uint2*)&g_h1h[(long)gr * 128 + cq] =
                f4_to_h4(make_float4(u0.x, u1.x, u2.x, u3.x));
        if (gr + 1 < NN)
            *(uint2*)&g_h1h[(long)(gr + 1) * 128 + cq] =
                f4_to_h4(make_float4(u0.y, u1.y, u2.y, u3.y));
    }
}

// ---------------- GEMM2: [N,128] x [128,32] -> g_h2h (fp16) -----------------
__global__ __launch_bounds__(128) void k_gemm2(const float* __restrict__ W) {
    __shared__ float xs[32][130];
    __shared__ __align__(16) float Ws[32][32];
    int tid = threadIdx.x, lane = tid & 31, wid = tid >> 5;
    int row0 = blockIdx.x * 128;
    int rbase = wid * 32 + (lane >> 3) * 8;
    int cq = (lane & 7) * 4;
    ull acc[4][4];
#pragma unroll
    for (int p = 0; p < 4; p++)
#pragma unroll
        for (int c = 0; c < 4; c++) acc[p][c] = 0ULL;

    for (int kt = 0; kt < 4; kt++) {
#pragma unroll
        for (int i = 0; i < 32; i++) {
            int idx = tid + 128 * i;
            int c = idx & 31, r = idx >> 5;
            int gr = row0 + r;
            xs[c][r] = (gr < NN) ? g_out1[(long)gr * 128 + kt * 32 + c] : 0.f;
        }
#pragma unroll
        for (int i = 0; i < 8; i++) {
            int idx = tid + 128 * i;
            int c = idx & 31, kr = idx >> 5;
            Ws[kr][c] = W[(kt * 32 + kr) * 32 + c];
        }
        __syncthreads();
#pragma unroll
        for (int kk = 0; kk < 32; kk++) {
            ull a0 = *(const ull*)&xs[kk][rbase + 0];
            ull a1 = *(const ull*)&xs[kk][rbase + 2];
            ull a2 = *(const ull*)&xs[kk][rbase + 4];
            ull a3 = *(const ull*)&xs[kk][rbase + 6];
            float4 wv = *(const float4*)&Ws[kk][cq];
            ull b0 = pack2(wv.x, wv.x);
            ull b1 = pack2(wv.y, wv.y);
            ull b2 = pack2(wv.z, wv.z);
            ull b3 = pack2(wv.w, wv.w);
            fma2(acc[0][0], a0, b0); fma2(acc[0][1], a0, b1);
            fma2(acc[0][2], a0, b2); fma2(acc[0][3], a0, b3);
            fma2(acc[1][0], a1, b0); fma2(acc[1][1], a1, b1);
            fma2(acc[1][2], a1, b2); fma2(acc[1][3], a1, b3);
            fma2(acc[2][0], a2, b0); fma2(acc[2][1], a2, b1);
            fma2(acc[2][2], a2, b2); fma2(acc[2][3], a2, b3);
            fma2(acc[3][0], a3, b0); fma2(acc[3][1], a3, b1);
            fma2(acc[3][2], a3, b2); fma2(acc[3][3], a3, b3);
        }
        __syncthreads();
    }
#pragma unroll
    for (int p = 0; p < 4; p++) {
        float2 u0 = unpack2(acc[p][0]), u1 = unpack2(acc[p][1]);
        float2 u2 = unpack2(acc[p][2]), u3 = unpack2(acc[p][3]);
        int gr = row0 + rbase + 2 * p;
        if (gr < NN)
            *(uint2*)&g_h2h[(long)gr * 32 + cq] =
                f4_to_h4(make_float4(u0.x, u1.x, u2.x, u3.x));
        if (gr + 1 < NN)
            *(uint2*)&g_h2h[(long)(gr + 1) * 32 + cq] =
                f4_to_h4(make_float4(u0.y, u1.y, u2.y, u3.y));
    }
}

// ---------------- attention coefficients ------------------------------------
__global__ __launch_bounds__(128) void k_coef1(const float* __restrict__ a_src,
                                               const float* __restrict__ a_dst) {
    int wid = threadIdx.x >> 5, lane = threadIdx.x & 31;
    int n = blockIdx.x * 4 + wid;
    if (n >= NN) return;
    float ps[4], pd[4];
#pragma unroll
    for (int k = 0; k < 4; k++) {
        float hv = __half2float(g_h1h[(long)n * 128 + k * 32 + lane]);
        ps[k] = hv * __ldg(&a_src[k * 32 + lane]);
        pd[k] = hv * __ldg(&a_dst[k * 32 + lane]);
    }
#pragma unroll
    for (int o = 16; o > 0; o >>= 1) {
#pragma unroll
        for (int k = 0; k < 4; k++) {
            ps[k] += __shfl_xor_sync(0xffffffffu, ps[k], o);
            pd[k] += __shfl_xor_sync(0xffffffffu, pd[k], o);
        }
    }
    if (lane == 0) {
#pragma unroll
        for (int k = 0; k < 4; k++) {
            g_as1[n * 4 + k] = ps[k];
            g_ad1[n * 4 + k] = pd[k];
        }
    }
}

__global__ __launch_bounds__(128) void k_coef2(const float* __restrict__ a_src,
                                               const float* __restrict__ a_dst) {
    int wid = threadIdx.x >> 5, lane = threadIdx.x & 31;
    int n = blockIdx.x * 4 + wid;
    if (n >= NN) return;
    float hv = __half2float(g_h2h[(long)n * 32 + lane]);
    float ps = hv * __ldg(&a_src[lane]);
    float pd = hv * __ldg(&a_dst[lane]);
#pragma unroll
    for (int o = 16; o > 0; o >>= 1) {
        ps += __shfl_xor_sync(0xffffffffu, ps, o);
        pd += __shfl_xor_sync(0xffffffffu, pd, o);
    }
    if (lane == 0) {
        g_as2[n] = ps;
        g_ad2[n] = pd;
    }
}

// ---------------- layer-1 gather: warp per dst node, fp16 features ----------
// Softmax without max-subtraction: |e| << 80, exact here.
__global__ __launch_bounds__(256) void k_gat1(const float* __restrict__ b) {
    int wid = threadIdx.x >> 5, lane = threadIdx.x & 31;
    int n = blockIdx.x * 8 + wid;
    if (n >= NN) return;
    int head = lane >> 3;
    float ad_l = (lane < 4) ? g_ad1[n * 4 + lane] : 0.f;

    // self loop
    float w4 = 0.f, den4 = 0.f;
    if (lane < 4) {
        w4 = __expf(lrelu(g_as1[n * 4 + lane] + ad_l));
        den4 = w4;
    }
    float w = __shfl_sync(0xffffffffu, w4, head);
    float4 hv = h4_to_f4(*(const uint2*)&g_h1h[(long)n * 128 + lane * 4]);
    float4 acc;
    acc.x = w * hv.x; acc.y = w * hv.y; acc.z = w * hv.z; acc.w = w * hv.w;

    int beg = g_off[n], end = g_off[n + 1];
    int j = beg;
    for (; j + 4 <= end; j += 4) {
        int s0 = __ldg(&g_srcs[j + 0]);
        int s1 = __ldg(&g_srcs[j + 1]);
        int s2 = __ldg(&g_srcs[j + 2]);
        int s3 = __ldg(&g_srcs[j + 3]);
        uint2 p0 = *(const uint2*)&g_h1h[(long)s0 * 128 + lane * 4];
        uint2 p1 = *(const uint2*)&g_h1h[(long)s1 * 128 + lane * 4];
        uint2 p2 = *(const uint2*)&g_h1h[(long)s2 * 128 + lane * 4];
        uint2 p3 = *(const uint2*)&g_h1h[(long)s3 * 128 + lane * 4];
        float w0 = 0.f, w1 = 0.f, w2 = 0.f, w3 = 0.f;
        if (lane < 4) {
            w0 = __expf(lrelu(__ldg(&g_as1[s0 * 4 + lane]) + ad_l));
            w1 = __expf(lrelu(__ldg(&g_as1[s1 * 4 + lane]) + ad_l));
            w2 = __expf(lrelu(__ldg(&g_as1[s2 * 4 + lane]) + ad_l));
            w3 = __expf(lrelu(__ldg(&g_as1[s3 * 4 + lane]) + ad_l));
            den4 += (w0 + w1) + (w2 + w3);
        }
        float ww0 = __shfl_sync(0xffffffffu, w0, head);
        float ww1 = __shfl_sync(0xffffffffu, w1, head);
        float ww2 = __shfl_sync(0xffffffffu, w2, head);
        float ww3 = __shfl_sync(0xffffffffu, w3, head);
        float4 h0 = h4_to_f4(p0), h1 = h4_to_f4(p1);
        float4 h2 = h4_to_f4(p2), h3 = h4_to_f4(p3);
        acc.x += ww0 * h0.x + ww1 * h1.x + ww2 * h2.x + ww3 * h3.x;
        acc.y += ww0 * h0.y + ww1 * h1.y + ww2 * h2.y + ww3 * h3.y;
        acc.z += ww0 * h0.z + ww1 * h1.z + ww2 * h2.z + ww3 * h3.z;
        acc.w += ww0 * h0.w + ww1 * h1.w + ww2 * h2.w + ww3 * h3.w;
    }
    for (; j < end; j++) {
        int s = __ldg(&g_srcs[j]);
        float wv = 0.f;
        if (lane < 4) {
            wv = __expf(lrelu(__ldg(&g_as1[s * 4 + lane]) + ad_l));
            den4 += wv;
        }
        float ww = __shfl_sync(0xffffffffu, wv, head);
        float4 h = h4_to_f4(*(const uint2*)&g_h1h[(long)s * 128 + lane * 4]);
        acc.x += ww * h.x; acc.y += ww * h.y; acc.z += ww * h.z; acc.w += ww * h.w;
    }
    float den = __shfl_sync(0xffffffffu, den4, head);
    float inv = 1.f / den;
    float4 bb = *(const float4*)&b[lane * 4];
    float4 o;
    o.x = fmaxf(acc.x * inv + bb.x, 0.f);
    o.y = fmaxf(acc.y * inv + bb.y, 0.f);
    o.z = fmaxf(acc.z * inv + bb.z, 0.f);
    o.w = fmaxf(acc.w * inv + bb.w, 0.f);
    *(float4*)&g_out1[(long)n * 128 + lane * 4] = o;
}

// ---------------- layer-2 gather: warp per dst node, fp16 features ----------
__global__ __launch_bounds__(256) void k_gat2(float* __restrict__ out,
                                              const float* __restrict__ b) {
    int wid = threadIdx.x >> 5, lane = threadIdx.x & 31;
    int n = blockIdx.x * 8 + wid;
    if (n >= NN) return;
    float adv = g_ad2[n];

    float w0s = 0.f, den = 0.f;
    if (lane == 0) {
        w0s = __expf(lrelu(g_as2[n] + adv));
        den = w0s;
    }
    float w = __shfl_sync(0xffffffffu, w0s, 0);
    float acc = w * __half2float(g_h2h[(long)n * 32 + lane]);

    int beg = g_off[n], end = g_off[n + 1];
    int j = beg;
    for (; j + 4 <= end; j += 4) {
        int s0 = __ldg(&g_srcs[j + 0]);
        int s1 = __ldg(&g_srcs[j + 1]);
        int s2 = __ldg(&g_srcs[j + 2]);
        int s3 = __ldg(&g_srcs[j + 3]);
        float h0 = __half2float(__ldg(&g_h2h[(long)s0 * 32 + lane]));
        float h1 = __half2float(__ldg(&g_h2h[(long)s1 * 32 + lane]));
        float h2 = __half2float(__ldg(&g_h2h[(long)s2 * 32 + lane]));
        float h3 = __half2float(__ldg(&g_h2h[(long)s3 * 32 + lane]));
        float wv = 0.f;
        if (lane < 4) {
            int ss = (lane == 0) ? s0 : (lane == 1) ? s1 : (lane == 2) ? s2 : s3;
            wv = __expf(lrelu(__ldg(&g_as2[ss]) + adv));
        }
        float ww0 = __shfl_sync(0xffffffffu, wv, 0);
        float ww1 = __shfl_sync(0xffffffffu, wv, 1);
        float ww2 = __shfl_sync(0xffffffffu, wv, 2);
        float ww3 = __shfl_sync(0xffffffffu, wv, 3);
        if (lane == 0) den += (ww0 + ww1) + (ww2 + ww3);
        acc += ww0 * h0 + ww1 * h1 + ww2 * h2 + ww3 * h3;
    }
    for (; j < end; j++) {
        int s = __ldg(&g_srcs[j]);
        float wv = 0.f;
        if (lane == 0) {
            wv = __expf(lrelu(__ldg(&g_as2[s]) + adv));
            den += wv;
        }
        float ww = __shfl_sync(0xffffffffu, wv, 0);
        acc += ww * __half2float(__ldg(&g_h2h[(long)s * 32 + lane]));
    }
    float d = __shfl_sync(0xffffffffu, den, 0);
    out[(long)n * 32 + lane] = acc / d + __ldg(&b[lane]);
}

// ---------------- launch ----------------------------------------------------
extern "C" void kernel_launch(void* const* d_in, const int* in_sizes, int n_in,
                              void* d_out, int out_size) {
    const float* x   = (const float*)d_in[0];
    const int*   ei  = (const int*)d_in[1];
    const float* W1  = (const float*)d_in[2];
    const float* as1 = (const float*)d_in[3];
    const float* ad1 = (const float*)d_in[4];
    const float* b1  = (const float*)d_in[5];
    const float* W2  = (const float*)d_in[6];
    const float* as2 = (const float*)d_in[7];
    const float* ad2 = (const float*)d_in[8];
    const float* b2  = (const float*)d_in[9];
    float* out = (float*)d_out;

    k_zero_cnt<<<(NN + 255) / 256, 256>>>();
    k_hist<<<(EE + 255) / 256, 256>>>(ei);
    k_gemm1<<<(NN + 63) / 64, 256>>>(x, W1);
    k_scan1<<<SCAN_NB, 512>>>();
    k_scan2<<<1, 256>>>();
    k_scan3<<<SCAN_NB, 512>>>();
    k_scatter<<<(EE + 255) / 256, 256>>>(ei);
    k_coef1<<<(NN + 3) / 4, 128>>>(as1, ad1);
    k_gat1<<<(NN + 7) / 8, 256>>>(b1);
    k_gemm2<<<(NN + 127) / 128, 128>>>(W2);
    k_coef2<<<(NN + 3) / 4, 128>>>(as2, ad2);
    k_gat2<<<(NN + 7) / 8, 256>>>(out, b2);
}